// round 16
// baseline (speedup 1.0000x reference)
#include <cuda_runtime.h>
#include <cuda_bf16.h>
#include <math.h>
#include <stdint.h>

#define NB 4
#define NC 256
#define HWP 25600
#define NS 1024
#define NT 4096   // NB*NS
#define GRID 148
#define NPAIR 36

typedef __nv_bfloat16 bf16;

__device__ __forceinline__ void cp16(void* sdst, const void* gsrc) {
    uint32_t s = (uint32_t)__cvta_generic_to_shared(sdst);
    asm volatile("cp.async.cg.shared.global [%0], [%1], 16;" :: "r"(s), "l"(gsrc));
}
#define CP_COMMIT() asm volatile("cp.async.commit_group;")
#define CP_WAIT2()  asm volatile("cp.async.wait_group 2;")

__device__ __forceinline__ void ldsm_x4(uint32_t& r0, uint32_t& r1, uint32_t& r2, uint32_t& r3,
                                        uint32_t addr) {
    asm volatile("ldmatrix.sync.aligned.m8n8.x4.shared.b16 {%0,%1,%2,%3}, [%4];"
                 : "=r"(r0), "=r"(r1), "=r"(r2), "=r"(r3) : "r"(addr));
}

// ---------- scratch ----------
__device__ __align__(16) bf16  d_Gbf[(size_t)NT*NC];   // gathered feats, [col][c]
__device__ __align__(16) bf16  d_Hbf[(size_t)NT*NC];   // hidden,         [col][m]
__device__ __align__(16) bf16  d_Ptbf[(size_t)NT*NC];  // proj (unnorm),  [col][m]
__device__ __align__(16) bf16  d_w1bf[NC*NC];
__device__ __align__(16) bf16  d_w2bf[NC*NC];
__device__ __align__(16) bf16  d_wa1bf[64*NC];
__device__ float d_attn[NT];
__device__ float d_ss[NT];
__device__ int   d_idx[NT];
__device__ int   d_sel[NT];
__device__ int   d_spv[NT];
__device__ int   d_vlist[NT];
__device__ int   d_ilist[NT];
__device__ float d_rowA[NT];
__device__ float d_rowB[NT];
__device__ float d_rowD[NT];
__device__ int   d_bar;

// ---------- global spin barrier (all GRID blocks resident) ----------
__device__ __forceinline__ void gbar(int target) {
    __syncthreads();
    if (threadIdx.x == 0) {
        __threadfence();
        atomicAdd(&d_bar, 1);
        while (((volatile int*)&d_bar)[0] < target) { }
        __threadfence();
    }
    __syncthreads();
}

// ---------- fused selection (blocks 0-3) + weight bf16 convert (blocks 4-39) ----------
__global__ void k_prep(const long long* __restrict__ labels, const long long* __restrict__ sp,
                       const float* __restrict__ w1, const float* __restrict__ w2,
                       const float* __restrict__ wa1) {
    int blk = blockIdx.x, t = threadIdx.x;   // 1024 threads
    if (blk >= NB) {
        int i = ((blk - NB)*1024 + t)*4;
        const float* src; bf16* dst; int off;
        if (i < 65536)        { src = w1;  dst = d_w1bf;  off = i; }
        else if (i < 131072)  { src = w2;  dst = d_w2bf;  off = i - 65536; }
        else                  { src = wa1; dst = d_wa1bf; off = i - 131072; }
        float4 v = *(const float4*)&src[off];
        __nv_bfloat162 lo = __floats2bfloat162_rn(v.x, v.y);
        __nv_bfloat162 hi = __floats2bfloat162_rn(v.z, v.w);
        *(uint2*)&dst[off] = make_uint2(*(uint32_t*)&lo, *(uint32_t*)&hi);
        return;
    }
    int b = blk;
    if (b == 0 && t == 0) d_bar = 0;
    const long long* lb = labels + (long long)b*HWP;
    int base = t*25;
    unsigned flags = 0; int cnt = 0;
    #pragma unroll
    for (int j = 0; j < 25; j++) {
        int f = (lb[base+j] == 1);
        flags |= (unsigned)f << j; cnt += f;
    }
    __shared__ int wsum[32];
    __shared__ int s_nv;
    int lane = t & 31, w = t >> 5;
    int incl = cnt;
    #pragma unroll
    for (int o = 1; o < 32; o <<= 1) {
        int n = __shfl_up_sync(0xffffffffu, incl, o);
        if (lane >= o) incl += n;
    }
    if (lane == 31) wsum[w] = incl;
    __syncthreads();
    if (t < 32) {
        int v = wsum[t]; int inc2 = v;
        #pragma unroll
        for (int o = 1; o < 32; o <<= 1) {
            int n = __shfl_up_sync(0xffffffffu, inc2, o);
            if (t >= o) inc2 += n;
        }
        wsum[t] = inc2 - v;
        if (t == 31) s_nv = inc2;
    }
    __syncthreads();
    int v_run = (incl - cnt) + wsum[w];
    #pragma unroll
    for (int j = 0; j < 25; j++) {
        int p = base + j;
        if ((flags >> j) & 1u) {
            if (v_run < NS) d_vlist[b*NS + v_run] = p;
            v_run++;
        } else {
            int ir = p - v_run;
            if (ir < NS) d_ilist[b*NS + ir] = p;
        }
    }
    __syncthreads();
    int nv = s_nv; if (nv > NS) nv = NS;
    int s = t;
    int p, se;
    if (s < nv) { p = d_vlist[b*NS + s];        se = 1; }
    else        { p = d_ilist[b*NS + (s - nv)]; se = 0; }
    int col = b*NS + s;
    d_idx[col] = p;
    d_sel[col] = se;
    d_spv[col] = (int)sp[(long long)b*HWP + p];
    d_rowA[col] = 0.f; d_rowB[col] = 0.f; d_rowD[col] = 0.f; d_ss[col] = 0.f;
}

// ---------- mma mainloop: 64x64 tile, K=256, 4-stage cp.async, ldmatrix fragments ----------
__device__ __forceinline__ void mma_mainloop(const bf16* __restrict__ A,
                                             const bf16* __restrict__ X,
                                             bf16* sA, bf16* sB,
                                             int m0, int n0, float acc[2][2][4]) {
    int t = threadIdx.x;
    int w = t >> 5, lane = t & 31;
    int wm = w >> 2, wn = w & 3;
    int frow = t >> 2, fchk = (t & 3)*8;
    const bf16* gA = &A[(size_t)(m0+frow)*NC + fchk];
    const bf16* gB = &X[(size_t)(n0+frow)*NC + fchk];
    #pragma unroll
    for (int pc = 0; pc < 3; pc++) {
        cp16(&sA[pc*2560 + frow*40 + fchk], gA + pc*32);
        cp16(&sB[pc*2560 + frow*40 + fchk], gB + pc*32);
        CP_COMMIT();
    }
    uint32_t sAb = (uint32_t)__cvta_generic_to_shared(sA);
    uint32_t sBb = (uint32_t)__cvta_generic_to_shared(sB);
    int lane7 = lane & 7;
    uint32_t aoff[2];
    #pragma unroll
    for (int mt = 0; mt < 2; mt++) {
        int rb = wm*32 + mt*16;
        aoff[mt] = ((rb + ((lane>>3)&1)*8 + lane7)*40 + (lane>>4)*8)*2;
    }
    uint32_t boff = ((wn*16 + ((lane>>4)&1)*8 + lane7)*40 + ((lane>>3)&1)*8)*2;

    for (int kc = 0; kc < 8; kc++) {
        int cur = kc & 3;
        CP_WAIT2();
        __syncthreads();
        if (kc + 3 < 8) {
            int nxt = (kc + 3) & 3;
            cp16(&sA[nxt*2560 + frow*40 + fchk], gA + (kc+3)*32);
            cp16(&sB[nxt*2560 + frow*40 + fchk], gB + (kc+3)*32);
        }
        CP_COMMIT();
        uint32_t cAa = sAb + cur*5120;
        uint32_t cBa = sBb + cur*5120;
        #pragma unroll
        for (int ks = 0; ks < 2; ks++) {
            uint32_t kbB = ks*32;
            uint32_t a[2][4], bb[2][2];
            #pragma unroll
            for (int mt = 0; mt < 2; mt++)
                ldsm_x4(a[mt][0], a[mt][1], a[mt][2], a[mt][3], cAa + aoff[mt] + kbB);
            ldsm_x4(bb[0][0], bb[0][1], bb[1][0], bb[1][1], cBa + boff + kbB);
            #pragma unroll
            for (int mt = 0; mt < 2; mt++)
                #pragma unroll
                for (int nt = 0; nt < 2; nt++)
                    asm volatile(
                        "mma.sync.aligned.m16n8k16.row.col.f32.bf16.bf16.f32 "
                        "{%0,%1,%2,%3}, {%4,%5,%6,%7}, {%8,%9}, {%0,%1,%2,%3};"
                        : "+f"(acc[mt][nt][0]), "+f"(acc[mt][nt][1]),
                          "+f"(acc[mt][nt][2]), "+f"(acc[mt][nt][3])
                        : "r"(a[mt][0]), "r"(a[mt][1]), "r"(a[mt][2]), "r"(a[mt][3]),
                          "r"(bb[nt][0]), "r"(bb[nt][1]));
        }
    }
}

// ---------- transposed bf16 store epilogue ----------
template<bool RELU, bool SS>
__device__ __forceinline__ void store_T(float acc[2][2][4], const float* __restrict__ bias,
                                        bf16* sT /*64 x 72*/, float* s_ss,
                                        bf16* __restrict__ Y, int m0, int n0) {
    int t = threadIdx.x;
    int w = t >> 5, lane = t & 31;
    int g = lane >> 2, tig = lane & 3;
    int wm = w >> 2, wn = w & 3;
    if (SS && t < 64) s_ss[t] = 0.f;
    __syncthreads();
    #pragma unroll
    for (int mt = 0; mt < 2; mt++) {
        #pragma unroll
        for (int half = 0; half < 2; half++) {
            int r = wm*32 + mt*16 + half*8 + g;
            float bv = bias[m0 + r];
            #pragma unroll
            for (int nt = 0; nt < 2; nt++) {
                #pragma unroll
                for (int c = 0; c < 2; c++) {
                    int cl = wn*16 + nt*8 + tig*2 + c;
                    float v = acc[mt][nt][half*2 + c] + bv;
                    if (RELU) v = fmaxf(v, 0.f);
                    sT[cl*72 + r] = __float2bfloat16(v);
                }
            }
        }
    }
    __syncthreads();
    #pragma unroll
    for (int i = 0; i < 2; i++) {
        int e = t*2 + i;
        int row = e >> 3, chk = (e & 7)*8;
        uint4 v = *(uint4*)&sT[row*72 + chk];
        *(uint4*)&Y[(size_t)(n0+row)*NC + m0 + chk] = v;
        if (SS) {
            bf16* h = (bf16*)&v;
            float p = 0.f;
            #pragma unroll
            for (int q = 0; q < 8; q++) {
                float f = __bfloat162float(h[q]);
                p = fmaf(f, f, p);
            }
            atomicAdd(&s_ss[row], p);
        }
    }
    if (SS) {
        __syncthreads();
        if (t < 64) atomicAdd(&d_ss[n0 + t], s_ss[t]);
    }
}

// ---------- persistent mega kernel: gather -> mma1+attn -> mma2 -> sim -> final ----------
#define MEGA_SMEM (4*10240*2)

__global__ __launch_bounds__(256) void k_mega(float* __restrict__ out,
                      const float* __restrict__ feats,
                      const float* __restrict__ b1, const float* __restrict__ ba1,
                      const float* __restrict__ wa2, const float* __restrict__ ba2,
                      const float* __restrict__ b2) {
    extern __shared__ __align__(16) char dbuf[];
    __shared__ float sRed[2][64];
    __shared__ float s_ss[64];
    __shared__ int   spJ[128];
    __shared__ int   seJ[128];
    __shared__ float wJ[128];
    __shared__ float rnJ[128];
    __shared__ float stageC[3][4][128];
    __shared__ float red[256];
    __shared__ float s_num, s_ps;
    int bid = blockIdx.x, t = threadIdx.x;

    // ---- phase 0: gather feats -> Gbf[col][c] bf16 ----
    for (int tile = bid; tile < 256; tile += GRID) {
        int sb = tile & 3, cb = (tile >> 2) & 15, b = tile >> 6;
        int s = sb*256 + t;
        int c0 = cb*16;
        int col = b*NS + s;
        int p = d_idx[col];
        const float* fb = feats + ((long long)b*NC + c0)*HWP + p;
        uint32_t pk[8];
        #pragma unroll
        for (int cc = 0; cc < 8; cc++) {
            float v0 = __ldg(&fb[(long long)(2*cc  )*HWP]);
            float v1 = __ldg(&fb[(long long)(2*cc+1)*HWP]);
            __nv_bfloat162 pr = __floats2bfloat162_rn(v0, v1);
            pk[cc] = *(uint32_t*)&pr;
        }
        uint4* dst = (uint4*)&d_Gbf[(size_t)col*NC + c0];
        dst[0] = make_uint4(pk[0], pk[1], pk[2], pk[3]);
        dst[1] = make_uint4(pk[4], pk[5], pk[6], pk[7]);
    }
    gbar(GRID);

    // ---- phase A: gemm1 + attn (320 tiles) ----
    {
        bf16* sA = (bf16*)dbuf;
        bf16* sB = (bf16*)(dbuf + 20480);
        bf16* sT = (bf16*)dbuf;
        for (int tile = bid; tile < 320; tile += GRID) {
            __syncthreads();
            int x = tile & 63, y = tile >> 6;
            int n0 = x*64;
            float acc[2][2][4] = {};
            if (y < 4) {
                int m0 = y*64;
                mma_mainloop(d_w1bf, d_Gbf, sA, sB, m0, n0, acc);
                store_T<true, false>(acc, b1, sT, nullptr, d_Hbf, m0, n0);
            } else {
                mma_mainloop(d_wa1bf, d_Gbf, sA, sB, 0, n0, acc);
                int w = t >> 5, lane = t & 31;
                int g = lane >> 2, tig = lane & 3;
                int wm = w >> 2, wn = w & 3;
                float part[2][2] = {};
                #pragma unroll
                for (int mt = 0; mt < 2; mt++) {
                    #pragma unroll
                    for (int half = 0; half < 2; half++) {
                        int r = wm*32 + mt*16 + half*8 + g;
                        float bm = ba1[r], wmv = wa2[r];
                        #pragma unroll
                        for (int nt = 0; nt < 2; nt++)
                            #pragma unroll
                            for (int c = 0; c < 2; c++)
                                part[nt][c] = fmaf(wmv, fmaxf(acc[mt][nt][half*2+c] + bm, 0.f), part[nt][c]);
                    }
                }
                #pragma unroll
                for (int nt = 0; nt < 2; nt++)
                    #pragma unroll
                    for (int c = 0; c < 2; c++) {
                        part[nt][c] += __shfl_down_sync(0xffffffffu, part[nt][c], 16);
                        part[nt][c] += __shfl_down_sync(0xffffffffu, part[nt][c], 8);
                        part[nt][c] += __shfl_down_sync(0xffffffffu, part[nt][c], 4);
                    }
                if (g == 0) {
                    #pragma unroll
                    for (int nt = 0; nt < 2; nt++)
                        #pragma unroll
                        for (int c = 0; c < 2; c++)
                            sRed[wm][wn*16 + nt*8 + tig*2 + c] = part[nt][c];
                }
                __syncthreads();
                if (t < 64) {
                    float z = sRed[0][t] + sRed[1][t] + ba2[0];
                    d_attn[n0 + t] = 1.f / (1.f + expf(-z));
                }
            }
        }
    }
    gbar(2*GRID);

    // ---- phase B: gemm2 (256 tiles) ----
    {
        bf16* sA = (bf16*)dbuf;
        bf16* sB = (bf16*)(dbuf + 20480);
        bf16* sT = (bf16*)dbuf;
        for (int tile = bid; tile < 256; tile += GRID) {
            __syncthreads();
            int n0 = (tile & 63)*64, m0 = (tile >> 6)*64;
            float acc[2][2][4] = {};
            mma_mainloop(d_w2bf, d_Hbf, sA, sB, m0, n0, acc);
            store_T<false, true>(acc, b2, sT, s_ss, d_Ptbf, m0, n0);
        }
    }
    gbar(3*GRID);

    // ---- phase C: symmetric sim (144 tiles, one per block) ----
    if (bid < NPAIR*NB) {
        bf16* sA = (bf16*)dbuf;
        bf16* sB = (bf16*)(dbuf + 4*10240);
        int pid = bid % NPAIR, b = bid / NPAIR;
        int I = 0, rem = pid;
        while (rem >= (8 - I)) { rem -= (8 - I); I++; }
        int J = I + rem;
        int i0 = I*128, j0 = J*128;
        bool diag = (I == J);
        if (t < 128) {
            int cj = b*NS + j0 + t;
            spJ[t] = d_spv[cj]; seJ[t] = d_sel[cj]; wJ[t] = d_attn[cj];
            rnJ[t] = 1.f / fmaxf(sqrtf(d_ss[cj]), 1e-12f);
        }
        int w = t >> 5, lane = t & 31;
        int g = lane >> 2, tig = lane & 3;
        int wm = w >> 1, wn = w & 1;
        const bf16* TA = d_Ptbf + (size_t)(b*NS + i0)*NC;
        const bf16* TB = d_Ptbf + (size_t)(b*NS + j0)*NC;
        int lrow = t >> 1, lpart = (t & 1)*16;

        #pragma unroll
        for (int pc = 0; pc < 3; pc++) {
            int kk = pc*32;
            cp16(&sA[pc*5120 + lrow*40 + lpart],     &TA[lrow*NC + kk + lpart]);
            cp16(&sA[pc*5120 + lrow*40 + lpart + 8], &TA[lrow*NC + kk + lpart + 8]);
            cp16(&sB[pc*5120 + lrow*40 + lpart],     &TB[lrow*NC + kk + lpart]);
            cp16(&sB[pc*5120 + lrow*40 + lpart + 8], &TB[lrow*NC + kk + lpart + 8]);
            CP_COMMIT();
        }

        uint32_t sAb = (uint32_t)__cvta_generic_to_shared(sA);
        uint32_t sBb = (uint32_t)__cvta_generic_to_shared(sB);
        int lane7 = lane & 7;
        uint32_t aoff[2];
        #pragma unroll
        for (int mt = 0; mt < 2; mt++) {
            int rb = wm*32 + mt*16;
            aoff[mt] = ((rb + ((lane>>3)&1)*8 + lane7)*40 + (lane>>4)*8)*2;
        }
        uint32_t boff[4];
        #pragma unroll
        for (int pr = 0; pr < 4; pr++) {
            int nb = wn*64 + pr*16;
            boff[pr] = ((nb + ((lane>>4)&1)*8 + lane7)*40 + ((lane>>3)&1)*8)*2;
        }

        float acc[2][8][4] = {};
        for (int kc = 0; kc < 8; kc++) {
            int cur = kc & 3;
            CP_WAIT2();
            __syncthreads();
            if (kc + 3 < 8) {
                int nxt = (kc + 3) & 3;
                int kk = (kc+3)*32;
                cp16(&sA[nxt*5120 + lrow*40 + lpart],     &TA[lrow*NC + kk + lpart]);
                cp16(&sA[nxt*5120 + lrow*40 + lpart + 8], &TA[lrow*NC + kk + lpart + 8]);
                cp16(&sB[nxt*5120 + lrow*40 + lpart],     &TB[lrow*NC + kk + lpart]);
                cp16(&sB[nxt*5120 + lrow*40 + lpart + 8], &TB[lrow*NC + kk + lpart + 8]);
            }
            CP_COMMIT();
            uint32_t cAa = sAb + cur*10240;
            uint32_t cBa = sBb + cur*10240;
            #pragma unroll
            for (int ks = 0; ks < 2; ks++) {
                uint32_t kbB = ks*32;
                uint32_t a[2][4];
                #pragma unroll
                for (int mt = 0; mt < 2; mt++)
                    ldsm_x4(a[mt][0], a[mt][1], a[mt][2], a[mt][3], cAa + aoff[mt] + kbB);
                #pragma unroll
                for (int pr = 0; pr < 4; pr++) {
                    uint32_t b00, b01, b10, b11;
                    ldsm_x4(b00, b01, b10, b11, cBa + boff[pr] + kbB);
                    #pragma unroll
                    for (int mt = 0; mt < 2; mt++) {
                        asm volatile(
                            "mma.sync.aligned.m16n8k16.row.col.f32.bf16.bf16.f32 "
                            "{%0,%1,%2,%3}, {%4,%5,%6,%7}, {%8,%9}, {%0,%1,%2,%3};"
                            : "+f"(acc[mt][2*pr][0]), "+f"(acc[mt][2*pr][1]),
                              "+f"(acc[mt][2*pr][2]), "+f"(acc[mt][2*pr][3])
                            : "r"(a[mt][0]), "r"(a[mt][1]), "r"(a[mt][2]), "r"(a[mt][3]),
                              "r"(b00), "r"(b01));
                        asm volatile(
                            "mma.sync.aligned.m16n8k16.row.col.f32.bf16.bf16.f32 "
                            "{%0,%1,%2,%3}, {%4,%5,%6,%7}, {%8,%9}, {%0,%1,%2,%3};"
                            : "+f"(acc[mt][2*pr+1][0]), "+f"(acc[mt][2*pr+1][1]),
                              "+f"(acc[mt][2*pr+1][2]), "+f"(acc[mt][2*pr+1][3])
                            : "r"(a[mt][0]), "r"(a[mt][1]), "r"(a[mt][2]), "r"(a[mt][3]),
                              "r"(b10), "r"(b11));
                    }
                }
            }
        }

        float colA[8][2] = {}, colB[8][2] = {}, colD[8][2] = {};
        #pragma unroll
        for (int mt = 0; mt < 2; mt++) {
            #pragma unroll
            for (int half = 0; half < 2; half++) {
                int il = wm*32 + mt*16 + half*8 + g;
                int ci = b*NS + i0 + il;
                int gi = i0 + il;
                int si = d_sel[ci], spi = d_spv[ci];
                float wi = d_attn[ci];
                float ri = 1.f / fmaxf(sqrtf(d_ss[ci]), 1e-12f);
                float rA = 0.f, rB = 0.f, rD = 0.f;
                #pragma unroll
                for (int nt = 0; nt < 8; nt++) {
                    #pragma unroll
                    for (int c = 0; c < 2; c++) {
                        int jl = wn*64 + nt*8 + tig*2 + c;
                        float s = acc[mt][nt][half*2 + c] * ri * rnJ[jl];
                        float e = __expf(10.0f * s);      // 1/TEMP = 10
                        int sj = seJ[jl];
                        if (sj) rD += e;
                        if (!diag && si) colD[nt][c] += e;
                        if (si && sj && (gi != j0 + jl) && (spi == spJ[jl]) && (s > 0.7f)) {
                            float pw = wi * wJ[jl];
                            rB += pw; rA = fmaf(pw, s, rA);
                            if (!diag) { colB[nt][c] += pw; colA[nt][c] = fmaf(pw, s, colA[nt][c]); }
                        }
                    }
                }
                rA += __shfl_down_sync(0xffffffffu, rA, 2, 4);
                rA += __shfl_down_sync(0xffffffffu, rA, 1, 4);
                rB += __shfl_down_sync(0xffffffffu, rB, 2, 4);
                rB += __shfl_down_sync(0xffffffffu, rB, 1, 4);
                rD += __shfl_down_sync(0xffffffffu, rD, 2, 4);
                rD += __shfl_down_sync(0xffffffffu, rD, 1, 4);
                if (tig == 0) {
                    atomicAdd(&d_rowA[ci], rA);
                    atomicAdd(&d_rowB[ci], rB);
                    atomicAdd(&d_rowD[ci], rD);
                }
            }
        }
        if (!diag) {
            #pragma unroll
            for (int nt = 0; nt < 8; nt++) {
                #pragma unroll
                for (int c = 0; c < 2; c++) {
                    #pragma unroll
                    for (int off = 4; off <= 16; off <<= 1) {
                        colA[nt][c] += __shfl_down_sync(0xffffffffu, colA[nt][c], off);
                        colB[nt][c] += __shfl_down_sync(0xffffffffu, colB[nt][c], off);
                        colD[nt][c] += __shfl_down_sync(0xffffffffu, colD[nt][c], off);
                    }
                }
            }
            if (g == 0) {
                #pragma unroll
                for (int nt = 0; nt < 8; nt++) {
                    #pragma unroll
                    for (int c = 0; c < 2; c++) {
                        int jl = wn*64 + nt*8 + tig*2 + c;
                        stageC[0][wm][jl] = colA[nt][c];
                        stageC[1][wm][jl] = colB[nt][c];
                        stageC[2][wm][jl] = colD[nt][c];
                    }
                }
            }
            __syncthreads();
            if (t < 128) {
                float a0 = 0.f, b0 = 0.f, d0 = 0.f;
                #pragma unroll
                for (int ww = 0; ww < 4; ww++) {
                    a0 += stageC[0][ww][t]; b0 += stageC[1][ww][t]; d0 += stageC[2][ww][t];
                }
                int cj = b*NS + j0 + t;
                atomicAdd(&d_rowA[cj], a0);
                atomicAdd(&d_rowB[cj], b0);
                atomicAdd(&d_rowD[cj], d0);
            }
        }
    }
    gbar(4*GRID);

    // ---- final reduction (block 0) ----
    if (bid != 0) return;
    float totLoss = 0.f;
    int nHas = 0;
    for (int b2i = 0; b2i < NB; b2i++) {
        float num = 0.f, ps = 0.f;
        for (int i = t; i < NS; i += 256) {
            float Ai = d_rowA[b2i*NS+i], Bi = d_rowB[b2i*NS+i], Di = d_rowD[b2i*NS+i];
            float ld = logf(Di > 0.f ? Di : 1.f);
            num += Ai * 10.0f - ld * Bi;
            ps  += Bi;
        }
        red[t] = num; __syncthreads();
        for (int o = 128; o > 0; o >>= 1) { if (t < o) red[t] += red[t+o]; __syncthreads(); }
        if (t == 0) s_num = red[0];
        __syncthreads();
        red[t] = ps; __syncthreads();
        for (int o = 128; o > 0; o >>= 1) { if (t < o) red[t] += red[t+o]; __syncthreads(); }
        if (t == 0) s_ps = red[0];
        __syncthreads();
        if (t == 0) {
            if (s_ps > 0.f) {
                totLoss += -(0.1f/0.07f) * s_num / s_ps;
                nHas++;
            }
        }
        __syncthreads();
    }
    if (t == 0) out[0] = (nHas > 0) ? (totLoss / fmaxf((float)nHas, 1.f)) : 0.f;
}

extern "C" void kernel_launch(void* const* d_in, const int* in_sizes, int n_in,
                              void* d_out, int out_size) {
    const float*     feats  = (const float*)d_in[0];
    const long long* labels = (const long long*)d_in[1];
    const long long* sp     = (const long long*)d_in[2];
    const float*     w1     = (const float*)d_in[3];
    const float*     b1     = (const float*)d_in[4];
    const float*     w2     = (const float*)d_in[5];
    const float*     b2     = (const float*)d_in[6];
    const float*     wa1    = (const float*)d_in[7];
    const float*     ba1    = (const float*)d_in[8];
    const float*     wa2    = (const float*)d_in[9];
    const float*     ba2    = (const float*)d_in[10];
    float* out = (float*)d_out;

    static bool inited = false;
    if (!inited) {
        cudaFuncSetAttribute(k_mega, cudaFuncAttributeMaxDynamicSharedMemorySize, MEGA_SMEM);
        inited = true;
    }

    k_prep <<<NB + 36, 1024>>>(labels, sp, w1, w2, wa1);
    k_mega <<<GRID, 256, MEGA_SMEM>>>(out, feats, b1, ba1, wa2, ba2, b2);
}